// round 7
// baseline (speedup 1.0000x reference)
#include <cuda_runtime.h>

#define ALPHA 0.01f

typedef unsigned long long u64;

// ---------------- global scratch for x = relu(fc1) ----------------
__device__ float g_xscr[65536 * 64];   // 16 MB static device scratch

__device__ __forceinline__ float lrelu(float v) { return fmaxf(v, ALPHA * v); }
__device__ __forceinline__ float fsig(float v)  { return __fdividef(1.0f, 1.0f + __expf(-v)); }
__device__ __forceinline__ float ftanh(float v) { return 1.0f - __fdividef(2.0f, __expf(2.0f * v) + 1.0f); }

__device__ __forceinline__ u64 pack2(float lo, float hi) {
    u64 r; asm("mov.b64 %0, {%1, %2};" : "=l"(r) : "f"(lo), "f"(hi)); return r;
}
__device__ __forceinline__ void unpack2(u64 v, float& lo, float& hi) {
    asm("mov.b64 {%0, %1}, %2;" : "=f"(lo), "=f"(hi) : "l"(v));
}
__device__ __forceinline__ u64 fma2(u64 a, u64 b, u64 c) {
    u64 d; asm("fma.rn.f32x2 %0, %1, %2, %3;" : "=l"(d) : "l"(a), "l"(b), "l"(c)); return d;
}

// ================= Kernel A: tokens -> attention -> fc1 =================
#define NBA    256
#define ROWSA  128
// smem layout (float offsets)
#define A_WIN   0        // 1536
#define A_BIN   1536     // 192
#define A_WA1   1728     // 64
#define A_WA2   1792     // 64
#define A_WO1   1856     // 320
#define A_BO1   2176     // 32
#define A_WO2   2208     // 512
#define A_BO2   2720     // 16
#define A_WO3   2736     // 16
#define A_BO3   2752     // 1 (+3)
#define A_WFC1  2756     // 5760
#define A_BFC1  8516     // 64
#define A_OBS   8580     // 128*85 = 10880
#define A_WHX   19460    // 128*21 = 2688 (wh exchange, odd stride)
#define A_HPV   22148    // 128*5  = 640
#define A_TOT   22788    // floats = 91152 bytes

__global__ void __launch_bounds__(NBA, 2)
stageA_kernel(const float* __restrict__ g_obs,
              const float* __restrict__ w_in0, const float* __restrict__ b_in0,
              const float* __restrict__ w_in1, const float* __restrict__ b_in1,
              const float* __restrict__ w_in2, const float* __restrict__ b_in2,
              const float* __restrict__ g_W,  const float* __restrict__ g_a,
              const float* __restrict__ w_o1, const float* __restrict__ b_o1,
              const float* __restrict__ w_o2, const float* __restrict__ b_o2,
              const float* __restrict__ w_o3, const float* __restrict__ b_o3,
              const float* __restrict__ w_fc1, const float* __restrict__ b_fc1)
{
    extern __shared__ float sm[];
    const int tid  = threadIdx.x;
    const int lrow = tid & 127;
    const int half = tid >> 7;            // warp-uniform (warps 0-3 / 4-7)
    const int row  = blockIdx.x * ROWSA + lrow;

    #define CPY4(off, src, n) { const float4* s4_ = (const float4*)(src); \
                                float4* d4_ = (float4*)&sm[off]; \
                                for (int i = tid; i < (n)/4; i += NBA) d4_[i] = s4_[i]; }
    CPY4(A_WIN,        w_in0, 512);
    CPY4(A_WIN + 512,  w_in1, 512);
    CPY4(A_WIN + 1024, w_in2, 512);
    CPY4(A_BIN,        b_in0, 64);
    CPY4(A_BIN + 64,   b_in1, 64);
    CPY4(A_BIN + 128,  b_in2, 64);
    CPY4(A_WO1, w_o1, 320);  CPY4(A_BO1, b_o1, 32);
    CPY4(A_WO2, w_o2, 512);  CPY4(A_BO2, b_o2, 16);
    CPY4(A_WO3, w_o3, 16);
    CPY4(A_WFC1, w_fc1, 5760); CPY4(A_BFC1, b_fc1, 64);
    #undef CPY4
    if (tid == 0) sm[A_BO3] = b_o3[0];

    // Wa1 = W @ a[:64], Wa2 = W @ a[64:]
    if (tid < 128) {
        const int j = tid & 63;
        const float* av = g_a + ((tid < 64) ? 0 : 64);
        const float* wr = g_W + j * 64;
        float s = 0.f;
        #pragma unroll 8
        for (int m = 0; m < 64; ++m) s = fmaf(wr[m], av[m], s);
        sm[((tid < 64) ? A_WA1 : A_WA2) + j] = s;
    }

    // stage obs tile
    {
        const float4* src4 = (const float4*)(g_obs + (size_t)blockIdx.x * ROWSA * 85);
        float4* dst4 = (float4*)&sm[A_OBS];
        for (int i = tid; i < ROWSA * 85 / 4; i += NBA) dst4[i] = src4[i];
    }
    __syncthreads();

    const float* orow = &sm[A_OBS + lrow * 85];

    // ---------------- stage 1: 5 tokens per half ----------------
    #pragma unroll
    for (int tt = 0; tt < 5; ++tt) {
        const int sel = half ? ((tt < 4) ? 1 : 2) : 0;
        float o[8];
        #pragma unroll
        for (int f = 0; f < 8; ++f) {
            int idx = half * 40 + tt * 8 + 4 + f;       // (t*8+f+4) % 80
            if (idx >= 80) idx -= 80;
            o[f] = orow[idx];
        }
        const float4* w4   = (const float4*)&sm[A_WIN + sel * 512];
        const float4* b4   = (const float4*)&sm[A_BIN + sel * 64];
        const float4* wa14 = (const float4*)&sm[A_WA1];
        const float4* wa24 = (const float4*)&sm[A_WA2];
        float s1 = 0.f, s2 = 0.f;
        #pragma unroll 4
        for (int jv = 0; jv < 16; ++jv) {
            float4 acc = b4[jv];
            #pragma unroll
            for (int f = 0; f < 8; ++f) {
                float4 wv = w4[f * 16 + jv];
                acc.x = fmaf(o[f], wv.x, acc.x);
                acc.y = fmaf(o[f], wv.y, acc.y);
                acc.z = fmaf(o[f], wv.z, acc.z);
                acc.w = fmaf(o[f], wv.w, acc.w);
            }
            acc.x = lrelu(acc.x); acc.y = lrelu(acc.y);
            acc.z = lrelu(acc.z); acc.w = lrelu(acc.w);
            float4 a1 = wa14[jv], a2 = wa24[jv];
            s1 = fmaf(acc.x, a1.x, s1); s1 = fmaf(acc.y, a1.y, s1);
            s1 = fmaf(acc.z, a1.z, s1); s1 = fmaf(acc.w, a1.w, s1);
            s2 = fmaf(acc.x, a2.x, s2); s2 = fmaf(acc.y, a2.y, s2);
            s2 = fmaf(acc.z, a2.z, s2); s2 = fmaf(acc.w, a2.w, s2);
        }
        const int t = half * 5 + tt;
        sm[A_WHX + lrow * 21 + 2 * t]     = s1;
        sm[A_WHX + lrow * 21 + 2 * t + 1] = s2;
    }
    __syncthreads();

    float wh1[10], wh2[10];
    #pragma unroll
    for (int t = 0; t < 10; ++t) {
        wh1[t] = sm[A_WHX + lrow * 21 + 2 * t];
        wh2[t] = sm[A_WHX + lrow * 21 + 2 * t + 1];
    }

    // ---------------- stage 2: attention rows (3 / 2 per half) ----------------
    float mx1[5], dinv1[5];
    #pragma unroll
    for (int c = 0; c < 5; ++c) {
        float mx = -1e30f;
        #pragma unroll
        for (int r2 = 0; r2 < 5; ++r2) mx = fmaxf(mx, lrelu(wh1[5 + c] + wh2[r2]));
        float d = 0.f;
        #pragma unroll
        for (int r2 = 0; r2 < 5; ++r2) d += __expf(lrelu(wh1[5 + c] + wh2[r2]) - mx);
        mx1[c] = mx; dinv1[c] = __fdividef(1.0f, d);
    }

    #pragma unroll
    for (int rr = 0; rr < 3; ++rr) {
        if (half && rr == 2) break;
        const int r = half ? (3 + rr) : rr;
        const float w1r = half ? wh1[3 + rr] : wh1[rr];
        const float w2r = half ? wh2[3 + rr] : wh2[rr];
        float att[10];
        {
            float ev[5]; float mx = -1e30f;
            #pragma unroll
            for (int c = 0; c < 5; ++c) {
                float v = lrelu(w1r + wh2[5 + c]);
                ev[c] = v; mx = fmaxf(mx, v);
            }
            float d = 0.f;
            #pragma unroll
            for (int c = 0; c < 5; ++c) { float e_ = __expf(ev[c] - mx); att[c] = e_; d += e_; }
            float inv = __fdividef(1.0f, d);
            #pragma unroll
            for (int c = 0; c < 5; ++c) att[c] *= inv;
            #pragma unroll
            for (int c = 0; c < 5; ++c)
                att[5 + c] = __expf(lrelu(wh1[5 + c] + w2r) - mx1[c]) * dinv1[c];
        }
        float h1[32];
        {
            const float4* wv4 = (const float4*)&sm[A_WO1];
            const float4* bv4 = (const float4*)&sm[A_BO1];
            #pragma unroll
            for (int jv = 0; jv < 8; ++jv) {
                float4 acc = bv4[jv];
                #pragma unroll
                for (int k = 0; k < 10; ++k) {
                    float4 wv = wv4[k * 8 + jv];
                    acc.x = fmaf(att[k], wv.x, acc.x);
                    acc.y = fmaf(att[k], wv.y, acc.y);
                    acc.z = fmaf(att[k], wv.z, acc.z);
                    acc.w = fmaf(att[k], wv.w, acc.w);
                }
                h1[4*jv]   = lrelu(acc.x); h1[4*jv+1] = lrelu(acc.y);
                h1[4*jv+2] = lrelu(acc.z); h1[4*jv+3] = lrelu(acc.w);
            }
        }
        float h2v[16];
        {
            const float4* wv4 = (const float4*)&sm[A_WO2];
            const float4* bv4 = (const float4*)&sm[A_BO2];
            #pragma unroll
            for (int jv = 0; jv < 4; ++jv) {
                float4 acc = bv4[jv];
                #pragma unroll
                for (int k = 0; k < 32; ++k) {
                    float4 wv = wv4[k * 4 + jv];
                    acc.x = fmaf(h1[k], wv.x, acc.x);
                    acc.y = fmaf(h1[k], wv.y, acc.y);
                    acc.z = fmaf(h1[k], wv.z, acc.z);
                    acc.w = fmaf(h1[k], wv.w, acc.w);
                }
                h2v[4*jv]   = lrelu(acc.x); h2v[4*jv+1] = lrelu(acc.y);
                h2v[4*jv+2] = lrelu(acc.z); h2v[4*jv+3] = lrelu(acc.w);
            }
        }
        float v = sm[A_BO3];
        {
            const float4* wv4 = (const float4*)&sm[A_WO3];
            #pragma unroll
            for (int kv = 0; kv < 4; ++kv) {
                float4 wv = wv4[kv];
                v = fmaf(h2v[4*kv],   wv.x, v);
                v = fmaf(h2v[4*kv+1], wv.y, v);
                v = fmaf(h2v[4*kv+2], wv.z, v);
                v = fmaf(h2v[4*kv+3], wv.w, v);
            }
        }
        sm[A_HPV + lrow * 5 + r] = lrelu(v);
    }
    __syncthreads();

    float obs_out[5];
    {
        float hp[5];
        #pragma unroll
        for (int r = 0; r < 5; ++r) hp[r] = sm[A_HPV + lrow * 5 + r];
        float mx = fmaxf(fmaxf(fmaxf(hp[0], hp[1]), fmaxf(hp[2], hp[3])), hp[4]);
        float d = 0.f;
        #pragma unroll
        for (int r = 0; r < 5; ++r) { obs_out[r] = __expf(hp[r] - mx); d += obs_out[r]; }
        float inv = __fdividef(1.0f, d);
        #pragma unroll
        for (int r = 0; r < 5; ++r) obs_out[r] *= inv;
    }

    // ---------------- stage 3: fc1 half (32 outputs) in f32x2 ----------------
    const int jbase = half * 32;
    u64 a2[16];
    {
        const ulonglong2* bv2 = (const ulonglong2*)&sm[A_BFC1 + jbase];
        #pragma unroll
        for (int v = 0; v < 8; ++v) { ulonglong2 q = bv2[v]; a2[2*v] = q.x; a2[2*v+1] = q.y; }
    }
    #pragma unroll 1
    for (int k = 0; k < 85; ++k) {
        const u64 ok2 = pack2(orow[k], orow[k]);
        const ulonglong2* w2 = (const ulonglong2*)&sm[A_WFC1 + k * 64 + jbase];
        #pragma unroll
        for (int v = 0; v < 8; ++v) {
            ulonglong2 q = w2[v];
            a2[2*v]   = fma2(ok2, q.x, a2[2*v]);
            a2[2*v+1] = fma2(ok2, q.y, a2[2*v+1]);
        }
    }
    #pragma unroll
    for (int m = 0; m < 5; ++m) {
        const u64 om2 = pack2(obs_out[m], obs_out[m]);
        const ulonglong2* w2 = (const ulonglong2*)&sm[A_WFC1 + (85 + m) * 64 + jbase];
        #pragma unroll
        for (int v = 0; v < 8; ++v) {
            ulonglong2 q = w2[v];
            a2[2*v]   = fma2(om2, q.x, a2[2*v]);
            a2[2*v+1] = fma2(om2, q.y, a2[2*v+1]);
        }
    }
    {
        float4* xo4 = (float4*)&g_xscr[(size_t)row * 64 + jbase];
        #pragma unroll
        for (int v = 0; v < 8; ++v) {
            float x0, x1, x2v, x3;
            unpack2(a2[2*v], x0, x1);
            unpack2(a2[2*v+1], x2v, x3);
            xo4[v] = make_float4(fmaxf(x0, 0.f), fmaxf(x1, 0.f),
                                 fmaxf(x2v, 0.f), fmaxf(x3, 0.f));
        }
    }
}

// ================= Kernel B: GRU + q (f32x2) =================
#define NBB    512
#define ROWSB  256
#define XS     66        // x-tile stride in floats (8B aligned; conflict-free per phase)
// smem layout (float offsets)
// weight chunks: per (j, kk) 12 floats:
//   [0..3]  {wir[2k], wir[2k+1], whr[2k], whr[2k+1]}
//   [4..7]  {wiz[2k], wiz[2k+1], whz[2k], whz[2k+1]}
//   [8..11] {win[2k], win[2k+1], whn[2k], whn[2k+1]}
#define B_WG    0        // 64*32*12 = 24576
#define B_GB    24576    // 64*4 bias quads {br, bz, bni, bnh}
#define B_WFC2  24832    // 320
#define B_BFC2  25152    // 5 (+3)
#define B_XT    25160    // 256*66 = 16896 (even offset -> 8B aligned)
#define B_QP    42056    // 256*5 = 1280
#define B_TOT   43336    // floats = 173344 bytes

__global__ void __launch_bounds__(NBB, 1)
stageB_kernel(const float* __restrict__ g_hid,
              const float* __restrict__ w_ih, const float* __restrict__ w_hh,
              const float* __restrict__ b_ih, const float* __restrict__ b_hh,
              const float* __restrict__ w_fc2, const float* __restrict__ b_fc2,
              float* __restrict__ out_q, float* __restrict__ out_h)
{
    extern __shared__ float sm[];
    const int tid  = threadIdx.x;
    const int lrow = tid & 255;
    const int half = tid >> 8;            // warp-uniform (warps 0-7 / 8-15)
    const int row  = blockIdx.x * ROWSB + lrow;
    const int jbase = half * 32;

    // stage GRU weights into packed chunks
    for (int idx = tid; idx < 64 * 32; idx += NBB) {
        const int j  = idx >> 5;
        const int k0 = (idx & 31) * 2;
        float* dst = &sm[B_WG + idx * 12];
        dst[0]  = w_ih[(j)       * 64 + k0];
        dst[1]  = w_ih[(j)       * 64 + k0 + 1];
        dst[2]  = w_hh[(j)       * 64 + k0];
        dst[3]  = w_hh[(j)       * 64 + k0 + 1];
        dst[4]  = w_ih[(64 + j)  * 64 + k0];
        dst[5]  = w_ih[(64 + j)  * 64 + k0 + 1];
        dst[6]  = w_hh[(64 + j)  * 64 + k0];
        dst[7]  = w_hh[(64 + j)  * 64 + k0 + 1];
        dst[8]  = w_ih[(128 + j) * 64 + k0];
        dst[9]  = w_ih[(128 + j) * 64 + k0 + 1];
        dst[10] = w_hh[(128 + j) * 64 + k0];
        dst[11] = w_hh[(128 + j) * 64 + k0 + 1];
    }
    if (tid < 64) {
        const int j = tid;
        sm[B_GB + 4*j]     = b_ih[j]       + b_hh[j];
        sm[B_GB + 4*j + 1] = b_ih[64 + j]  + b_hh[64 + j];
        sm[B_GB + 4*j + 2] = b_ih[128 + j];
        sm[B_GB + 4*j + 3] = b_hh[128 + j];
    }
    for (int i = tid; i < 320; i += NBB) sm[B_WFC2 + i] = w_fc2[i];
    if (tid >= 64 && tid < 69) sm[B_BFC2 + tid - 64] = b_fc2[tid - 64];

    // stage x tile (coalesced global reads)
    {
        const float* src = &g_xscr[(size_t)blockIdx.x * ROWSB * 64];
        for (int i = tid; i < ROWSB * 64; i += NBB) {
            const int r = i >> 6, k = i & 63;
            sm[B_XT + r * XS + k] = src[i];
        }
    }

    // load h_in into packed registers (32 u64)
    const float* hid_row = g_hid + (size_t)row * 64;
    u64 hi2[32];
    {
        const float4* hp4 = (const float4*)hid_row;
        #pragma unroll
        for (int i = 0; i < 16; ++i) {
            float4 v = hp4[i];
            hi2[2*i]   = pack2(v.x, v.y);
            hi2[2*i+1] = pack2(v.z, v.w);
        }
    }
    __syncthreads();

    const u64* xrow2 = (const u64*)&sm[B_XT + lrow * XS];
    float hq0 = 0.f, hq1 = 0.f, hq2 = 0.f, hq3 = 0.f, hq4 = 0.f;
    if (!half) {
        hq0 = sm[B_BFC2];     hq1 = sm[B_BFC2 + 1]; hq2 = sm[B_BFC2 + 2];
        hq3 = sm[B_BFC2 + 3]; hq4 = sm[B_BFC2 + 4];
    }
    float* hrow = out_h + (size_t)row * 64;

    #pragma unroll 1
    for (int jj = 0; jj < 32; ++jj) {
        const int j = jbase + jj;
        const float4 gb = *(const float4*)&sm[B_GB + 4 * j];   // {br, bz, bni, bnh}
        const float* wj = &sm[B_WG + j * 384];                 // 32 chunks * 12 floats

        u64 ar = 0ull, az = 0ull, anx = 0ull, anh = 0ull;
        #pragma unroll
        for (int kk = 0; kk < 32; ++kk) {
            const ulonglong2 qr = *(const ulonglong2*)(wj + kk * 12);
            const ulonglong2 qz = *(const ulonglong2*)(wj + kk * 12 + 4);
            const ulonglong2 qn = *(const ulonglong2*)(wj + kk * 12 + 8);
            const u64 x2 = xrow2[kk];
            const u64 h2 = hi2[kk];
            ar  = fma2(x2, qr.x, ar);  ar  = fma2(h2, qr.y, ar);
            az  = fma2(x2, qz.x, az);  az  = fma2(h2, qz.y, az);
            anx = fma2(x2, qn.x, anx); anh = fma2(h2, qn.y, anh);
        }
        float al, ah;
        unpack2(ar, al, ah);
        const float r_ = fsig(al + ah + gb.x);
        unpack2(az, al, ah);
        const float z_ = fsig(al + ah + gb.y);
        float nxl, nxh, nhl, nhh;
        unpack2(anx, nxl, nxh);
        unpack2(anh, nhl, nhh);
        const float n_ = ftanh(fmaf(r_, nhl + nhh + gb.w, nxl + nxh + gb.z));

        const float hj = __ldg(hid_row + j);        // h_in[j] (L1/L2 hit)
        const float h_ = n_ + z_ * (hj - n_);
        hrow[j] = h_;
        hq0 = fmaf(h_, sm[B_WFC2 + j * 5],     hq0);
        hq1 = fmaf(h_, sm[B_WFC2 + j * 5 + 1], hq1);
        hq2 = fmaf(h_, sm[B_WFC2 + j * 5 + 2], hq2);
        hq3 = fmaf(h_, sm[B_WFC2 + j * 5 + 3], hq3);
        hq4 = fmaf(h_, sm[B_WFC2 + j * 5 + 4], hq4);
    }

    // combine q halves via smem
    if (half) {
        sm[B_QP + lrow * 5]     = hq0;
        sm[B_QP + lrow * 5 + 1] = hq1;
        sm[B_QP + lrow * 5 + 2] = hq2;
        sm[B_QP + lrow * 5 + 3] = hq3;
        sm[B_QP + lrow * 5 + 4] = hq4;
    }
    __syncthreads();
    if (!half) {
        float* qp = out_q + (size_t)row * 5;
        qp[0] = hq0 + sm[B_QP + lrow * 5];
        qp[1] = hq1 + sm[B_QP + lrow * 5 + 1];
        qp[2] = hq2 + sm[B_QP + lrow * 5 + 2];
        qp[3] = hq3 + sm[B_QP + lrow * 5 + 3];
        qp[4] = hq4 + sm[B_QP + lrow * 5 + 4];
    }
}

extern "C" void kernel_launch(void* const* d_in, const int* in_sizes, int n_in,
                              void* d_out, int out_size)
{
    const float* g_obs  = (const float*)d_in[0];
    const float* g_hid  = (const float*)d_in[1];
    const float* w_in0  = (const float*)d_in[2];
    const float* b_in0  = (const float*)d_in[3];
    const float* w_in1  = (const float*)d_in[4];
    const float* b_in1  = (const float*)d_in[5];
    const float* w_in2  = (const float*)d_in[6];
    const float* b_in2  = (const float*)d_in[7];
    const float* g_W    = (const float*)d_in[8];
    const float* g_a    = (const float*)d_in[9];
    const float* w_o1   = (const float*)d_in[10];
    const float* b_o1   = (const float*)d_in[11];
    const float* w_o2   = (const float*)d_in[12];
    const float* b_o2   = (const float*)d_in[13];
    const float* w_o3   = (const float*)d_in[14];
    const float* b_o3   = (const float*)d_in[15];
    const float* w_fc1  = (const float*)d_in[16];
    const float* b_fc1  = (const float*)d_in[17];
    const float* w_ih   = (const float*)d_in[18];
    const float* w_hh   = (const float*)d_in[19];
    const float* b_ih   = (const float*)d_in[20];
    const float* b_hh   = (const float*)d_in[21];
    const float* w_fc2  = (const float*)d_in[22];
    const float* b_fc2  = (const float*)d_in[23];

    float* out   = (float*)d_out;
    float* out_q = out;                          // q: (65536, 5)
    float* out_h = out + (size_t)65536 * 5;      // h: (65536, 64)

    const int smemA = A_TOT * 4;                 // 91152 B (2 blocks/SM)
    const int smemB = B_TOT * 4;                 // 173344 B
    cudaFuncSetAttribute(stageA_kernel, cudaFuncAttributeMaxDynamicSharedMemorySize, smemA);
    cudaFuncSetAttribute(stageB_kernel, cudaFuncAttributeMaxDynamicSharedMemorySize, smemB);

    stageA_kernel<<<65536 / ROWSA, NBA, smemA>>>(
        g_obs, w_in0, b_in0, w_in1, b_in1, w_in2, b_in2, g_W, g_a,
        w_o1, b_o1, w_o2, b_o2, w_o3, b_o3, w_fc1, b_fc1);

    stageB_kernel<<<65536 / ROWSB, NBB, smemB>>>(
        g_hid, w_ih, w_hh, b_ih, b_hh, w_fc2, b_fc2, out_q, out_h);
}

// round 8
// speedup vs baseline: 1.2275x; 1.2275x over previous
#include <cuda_runtime.h>

#define ALPHA 0.01f

typedef unsigned long long u64;

// ---------------- global scratch ----------------
__device__ float g_xscr[65536 * 64];            // 16 MB: x = relu(fc1)
__device__ float g_gates[(size_t)65536 * 256];  // 64 MB: GEMM output [r|z|gi_n|gh_n]

__device__ __forceinline__ float lrelu(float v) { return fmaxf(v, ALPHA * v); }
__device__ __forceinline__ float fsig(float v)  { return __fdividef(1.0f, 1.0f + __expf(-v)); }
__device__ __forceinline__ float ftanh(float v) { return 1.0f - __fdividef(2.0f, __expf(2.0f * v) + 1.0f); }

__device__ __forceinline__ u64 pack2(float lo, float hi) {
    u64 r; asm("mov.b64 %0, {%1, %2};" : "=l"(r) : "f"(lo), "f"(hi)); return r;
}
__device__ __forceinline__ void unpack2(u64 v, float& lo, float& hi) {
    asm("mov.b64 {%0, %1}, %2;" : "=f"(lo), "=f"(hi) : "l"(v));
}
__device__ __forceinline__ u64 fma2(u64 a, u64 b, u64 c) {
    u64 d; asm("fma.rn.f32x2 %0, %1, %2, %3;" : "=l"(d) : "l"(a), "l"(b), "l"(c)); return d;
}

// ================= Kernel A: tokens -> attention -> fc1 (unchanged) =================
#define NBA    256
#define ROWSA  128
#define A_WIN   0
#define A_BIN   1536
#define A_WA1   1728
#define A_WA2   1792
#define A_WO1   1856
#define A_BO1   2176
#define A_WO2   2208
#define A_BO2   2720
#define A_WO3   2736
#define A_BO3   2752
#define A_WFC1  2756
#define A_BFC1  8516
#define A_OBS   8580
#define A_WHX   19460
#define A_HPV   22148
#define A_TOT   22788

__global__ void __launch_bounds__(NBA, 2)
stageA_kernel(const float* __restrict__ g_obs,
              const float* __restrict__ w_in0, const float* __restrict__ b_in0,
              const float* __restrict__ w_in1, const float* __restrict__ b_in1,
              const float* __restrict__ w_in2, const float* __restrict__ b_in2,
              const float* __restrict__ g_W,  const float* __restrict__ g_a,
              const float* __restrict__ w_o1, const float* __restrict__ b_o1,
              const float* __restrict__ w_o2, const float* __restrict__ b_o2,
              const float* __restrict__ w_o3, const float* __restrict__ b_o3,
              const float* __restrict__ w_fc1, const float* __restrict__ b_fc1)
{
    extern __shared__ float sm[];
    const int tid  = threadIdx.x;
    const int lrow = tid & 127;
    const int half = tid >> 7;
    const int row  = blockIdx.x * ROWSA + lrow;

    #define CPY4(off, src, n) { const float4* s4_ = (const float4*)(src); \
                                float4* d4_ = (float4*)&sm[off]; \
                                for (int i = tid; i < (n)/4; i += NBA) d4_[i] = s4_[i]; }
    CPY4(A_WIN,        w_in0, 512);
    CPY4(A_WIN + 512,  w_in1, 512);
    CPY4(A_WIN + 1024, w_in2, 512);
    CPY4(A_BIN,        b_in0, 64);
    CPY4(A_BIN + 64,   b_in1, 64);
    CPY4(A_BIN + 128,  b_in2, 64);
    CPY4(A_WO1, w_o1, 320);  CPY4(A_BO1, b_o1, 32);
    CPY4(A_WO2, w_o2, 512);  CPY4(A_BO2, b_o2, 16);
    CPY4(A_WO3, w_o3, 16);
    CPY4(A_WFC1, w_fc1, 5760); CPY4(A_BFC1, b_fc1, 64);
    #undef CPY4
    if (tid == 0) sm[A_BO3] = b_o3[0];

    if (tid < 128) {
        const int j = tid & 63;
        const float* av = g_a + ((tid < 64) ? 0 : 64);
        const float* wr = g_W + j * 64;
        float s = 0.f;
        #pragma unroll 8
        for (int m = 0; m < 64; ++m) s = fmaf(wr[m], av[m], s);
        sm[((tid < 64) ? A_WA1 : A_WA2) + j] = s;
    }

    {
        const float4* src4 = (const float4*)(g_obs + (size_t)blockIdx.x * ROWSA * 85);
        float4* dst4 = (float4*)&sm[A_OBS];
        for (int i = tid; i < ROWSA * 85 / 4; i += NBA) dst4[i] = src4[i];
    }
    __syncthreads();

    const float* orow = &sm[A_OBS + lrow * 85];

    #pragma unroll
    for (int tt = 0; tt < 5; ++tt) {
        const int sel = half ? ((tt < 4) ? 1 : 2) : 0;
        float o[8];
        #pragma unroll
        for (int f = 0; f < 8; ++f) {
            int idx = half * 40 + tt * 8 + 4 + f;
            if (idx >= 80) idx -= 80;
            o[f] = orow[idx];
        }
        const float4* w4   = (const float4*)&sm[A_WIN + sel * 512];
        const float4* b4   = (const float4*)&sm[A_BIN + sel * 64];
        const float4* wa14 = (const float4*)&sm[A_WA1];
        const float4* wa24 = (const float4*)&sm[A_WA2];
        float s1 = 0.f, s2 = 0.f;
        #pragma unroll 4
        for (int jv = 0; jv < 16; ++jv) {
            float4 acc = b4[jv];
            #pragma unroll
            for (int f = 0; f < 8; ++f) {
                float4 wv = w4[f * 16 + jv];
                acc.x = fmaf(o[f], wv.x, acc.x);
                acc.y = fmaf(o[f], wv.y, acc.y);
                acc.z = fmaf(o[f], wv.z, acc.z);
                acc.w = fmaf(o[f], wv.w, acc.w);
            }
            acc.x = lrelu(acc.x); acc.y = lrelu(acc.y);
            acc.z = lrelu(acc.z); acc.w = lrelu(acc.w);
            float4 a1 = wa14[jv], a2 = wa24[jv];
            s1 = fmaf(acc.x, a1.x, s1); s1 = fmaf(acc.y, a1.y, s1);
            s1 = fmaf(acc.z, a1.z, s1); s1 = fmaf(acc.w, a1.w, s1);
            s2 = fmaf(acc.x, a2.x, s2); s2 = fmaf(acc.y, a2.y, s2);
            s2 = fmaf(acc.z, a2.z, s2); s2 = fmaf(acc.w, a2.w, s2);
        }
        const int t = half * 5 + tt;
        sm[A_WHX + lrow * 21 + 2 * t]     = s1;
        sm[A_WHX + lrow * 21 + 2 * t + 1] = s2;
    }
    __syncthreads();

    float wh1[10], wh2[10];
    #pragma unroll
    for (int t = 0; t < 10; ++t) {
        wh1[t] = sm[A_WHX + lrow * 21 + 2 * t];
        wh2[t] = sm[A_WHX + lrow * 21 + 2 * t + 1];
    }

    float mx1[5], dinv1[5];
    #pragma unroll
    for (int c = 0; c < 5; ++c) {
        float mx = -1e30f;
        #pragma unroll
        for (int r2 = 0; r2 < 5; ++r2) mx = fmaxf(mx, lrelu(wh1[5 + c] + wh2[r2]));
        float d = 0.f;
        #pragma unroll
        for (int r2 = 0; r2 < 5; ++r2) d += __expf(lrelu(wh1[5 + c] + wh2[r2]) - mx);
        mx1[c] = mx; dinv1[c] = __fdividef(1.0f, d);
    }

    #pragma unroll
    for (int rr = 0; rr < 3; ++rr) {
        if (half && rr == 2) break;
        const int r = half ? (3 + rr) : rr;
        const float w1r = half ? wh1[3 + rr] : wh1[rr];
        const float w2r = half ? wh2[3 + rr] : wh2[rr];
        float att[10];
        {
            float ev[5]; float mx = -1e30f;
            #pragma unroll
            for (int c = 0; c < 5; ++c) {
                float v = lrelu(w1r + wh2[5 + c]);
                ev[c] = v; mx = fmaxf(mx, v);
            }
            float d = 0.f;
            #pragma unroll
            for (int c = 0; c < 5; ++c) { float e_ = __expf(ev[c] - mx); att[c] = e_; d += e_; }
            float inv = __fdividef(1.0f, d);
            #pragma unroll
            for (int c = 0; c < 5; ++c) att[c] *= inv;
            #pragma unroll
            for (int c = 0; c < 5; ++c)
                att[5 + c] = __expf(lrelu(wh1[5 + c] + w2r) - mx1[c]) * dinv1[c];
        }
        float h1[32];
        {
            const float4* wv4 = (const float4*)&sm[A_WO1];
            const float4* bv4 = (const float4*)&sm[A_BO1];
            #pragma unroll
            for (int jv = 0; jv < 8; ++jv) {
                float4 acc = bv4[jv];
                #pragma unroll
                for (int k = 0; k < 10; ++k) {
                    float4 wv = wv4[k * 8 + jv];
                    acc.x = fmaf(att[k], wv.x, acc.x);
                    acc.y = fmaf(att[k], wv.y, acc.y);
                    acc.z = fmaf(att[k], wv.z, acc.z);
                    acc.w = fmaf(att[k], wv.w, acc.w);
                }
                h1[4*jv]   = lrelu(acc.x); h1[4*jv+1] = lrelu(acc.y);
                h1[4*jv+2] = lrelu(acc.z); h1[4*jv+3] = lrelu(acc.w);
            }
        }
        float h2v[16];
        {
            const float4* wv4 = (const float4*)&sm[A_WO2];
            const float4* bv4 = (const float4*)&sm[A_BO2];
            #pragma unroll
            for (int jv = 0; jv < 4; ++jv) {
                float4 acc = bv4[jv];
                #pragma unroll
                for (int k = 0; k < 32; ++k) {
                    float4 wv = wv4[k * 4 + jv];
                    acc.x = fmaf(h1[k], wv.x, acc.x);
                    acc.y = fmaf(h1[k], wv.y, acc.y);
                    acc.z = fmaf(h1[k], wv.z, acc.z);
                    acc.w = fmaf(h1[k], wv.w, acc.w);
                }
                h2v[4*jv]   = lrelu(acc.x); h2v[4*jv+1] = lrelu(acc.y);
                h2v[4*jv+2] = lrelu(acc.z); h2v[4*jv+3] = lrelu(acc.w);
            }
        }
        float v = sm[A_BO3];
        {
            const float4* wv4 = (const float4*)&sm[A_WO3];
            #pragma unroll
            for (int kv = 0; kv < 4; ++kv) {
                float4 wv = wv4[kv];
                v = fmaf(h2v[4*kv],   wv.x, v);
                v = fmaf(h2v[4*kv+1], wv.y, v);
                v = fmaf(h2v[4*kv+2], wv.z, v);
                v = fmaf(h2v[4*kv+3], wv.w, v);
            }
        }
        sm[A_HPV + lrow * 5 + r] = lrelu(v);
    }
    __syncthreads();

    float obs_out[5];
    {
        float hp[5];
        #pragma unroll
        for (int r = 0; r < 5; ++r) hp[r] = sm[A_HPV + lrow * 5 + r];
        float mx = fmaxf(fmaxf(fmaxf(hp[0], hp[1]), fmaxf(hp[2], hp[3])), hp[4]);
        float d = 0.f;
        #pragma unroll
        for (int r = 0; r < 5; ++r) { obs_out[r] = __expf(hp[r] - mx); d += obs_out[r]; }
        float inv = __fdividef(1.0f, d);
        #pragma unroll
        for (int r = 0; r < 5; ++r) obs_out[r] *= inv;
    }

    const int jbase = half * 32;
    u64 a2[16];
    {
        const ulonglong2* bv2 = (const ulonglong2*)&sm[A_BFC1 + jbase];
        #pragma unroll
        for (int v = 0; v < 8; ++v) { ulonglong2 q = bv2[v]; a2[2*v] = q.x; a2[2*v+1] = q.y; }
    }
    #pragma unroll 1
    for (int k = 0; k < 85; ++k) {
        const u64 ok2 = pack2(orow[k], orow[k]);
        const ulonglong2* w2 = (const ulonglong2*)&sm[A_WFC1 + k * 64 + jbase];
        #pragma unroll
        for (int v = 0; v < 8; ++v) {
            ulonglong2 q = w2[v];
            a2[2*v]   = fma2(ok2, q.x, a2[2*v]);
            a2[2*v+1] = fma2(ok2, q.y, a2[2*v+1]);
        }
    }
    #pragma unroll
    for (int m = 0; m < 5; ++m) {
        const u64 om2 = pack2(obs_out[m], obs_out[m]);
        const ulonglong2* w2 = (const ulonglong2*)&sm[A_WFC1 + (85 + m) * 64 + jbase];
        #pragma unroll
        for (int v = 0; v < 8; ++v) {
            ulonglong2 q = w2[v];
            a2[2*v]   = fma2(om2, q.x, a2[2*v]);
            a2[2*v+1] = fma2(om2, q.y, a2[2*v+1]);
        }
    }
    {
        float4* xo4 = (float4*)&g_xscr[(size_t)row * 64 + jbase];
        #pragma unroll
        for (int v = 0; v < 8; ++v) {
            float x0, x1, x2v, x3;
            unpack2(a2[2*v], x0, x1);
            unpack2(a2[2*v+1], x2v, x3);
            xo4[v] = make_float4(fmaxf(x0, 0.f), fmaxf(x1, 0.f),
                                 fmaxf(x2v, 0.f), fmaxf(x3, 0.f));
        }
    }
}

// ================= Kernel G: gate GEMM  G = [x|h] @ Wg^T =================
// G layout per row (256): [r_pre(64) | z_pre(64) | gi_n(64) | gh_n(64)]  (no biases)
// K layout: [x(64) | h(64)].  r/z use full K; gi_n uses K<64; gh_n uses K>=64.
#define G_THREADS 512
#define XP 130                      // Xs pitch
#define WP 258                      // Ws pitch
#define G_XS 0                      // 128*130 = 16640
#define G_WS 16640                  // 128*258 = 33024
#define G_TOT (16640 + 33024)       // 49664 floats = 198656 bytes

__global__ void __launch_bounds__(G_THREADS, 1)
gemm_kernel(const float* __restrict__ g_hid,
            const float* __restrict__ w_ih, const float* __restrict__ w_hh)
{
    extern __shared__ float sm[];
    float* Xs = &sm[G_XS];
    float* Ws = &sm[G_WS];
    const int tid = threadIdx.x;
    const size_t rb = (size_t)blockIdx.x * 128;

    // stage X tile: Xs[k][row], k<64 = x, k>=64 = h  (LDG coalesced; STS deg-2)
    for (int idx = tid; idx < 128 * 64; idx += G_THREADS) {
        const int r = idx >> 6, k = idx & 63;
        Xs[k * XP + r]        = g_xscr[(rb + r) * 64 + k];
        Xs[(64 + k) * XP + r] = g_hid[(rb + r) * 64 + k];
    }
    // stage W: Ws[k][gate]; lanes along k -> LDG coalesced
    for (int idx = tid; idx < 64 * 192; idx += G_THREADS) {
        const int k = idx & 63, t = idx >> 6;           // t = source gate row 0..191
        Ws[k * WP + t] = w_ih[t * 64 + k];              // k<64 block: r,z,gi_n
        const int dt = (t < 128) ? t : (t + 64);        // n-rows go to gh_n slots
        Ws[(64 + k) * WP + dt] = w_hh[t * 64 + k];      // k>=64 block: r,z,gh_n
    }
    __syncthreads();

    const int tr = tid >> 5;        // 0..15 -> rows [8tr, 8tr+8)
    const int l  = tid & 31;        // gate-pair lane

    u64 ac[32];
    #pragma unroll
    for (int i = 0; i < 32; ++i) ac[i] = 0ull;

    // ---- k < 64: blocks r(0), z(64), gi_n(128) ----
    #pragma unroll 2
    for (int k = 0; k < 64; ++k) {
        const float* ap = &Xs[k * XP + 8 * tr];
        const u64 a01 = *(const u64*)ap;
        const u64 a23 = *(const u64*)(ap + 2);
        const u64 a45 = *(const u64*)(ap + 4);
        const u64 a67 = *(const u64*)(ap + 6);
        const float* wp = &Ws[k * WP + 2 * l];
        const u64 b0 = *(const u64*)wp;
        const u64 b1 = *(const u64*)(wp + 64);
        const u64 b2 = *(const u64*)(wp + 128);
        float a0, a1, a2f, a3, a4, a5, a6, a7;
        unpack2(a01, a0, a1); unpack2(a23, a2f, a3);
        unpack2(a45, a4, a5); unpack2(a67, a6, a7);
        #define ROWF(i, av) { const u64 aa = pack2(av, av); \
            ac[4*i]   = fma2(aa, b0, ac[4*i]); \
            ac[4*i+1] = fma2(aa, b1, ac[4*i+1]); \
            ac[4*i+2] = fma2(aa, b2, ac[4*i+2]); }
        ROWF(0, a0) ROWF(1, a1) ROWF(2, a2f) ROWF(3, a3)
        ROWF(4, a4) ROWF(5, a5) ROWF(6, a6) ROWF(7, a7)
        #undef ROWF
    }
    // ---- k >= 64: blocks r(0), z(64), gh_n(192) ----
    #pragma unroll 2
    for (int k = 64; k < 128; ++k) {
        const float* ap = &Xs[k * XP + 8 * tr];
        const u64 a01 = *(const u64*)ap;
        const u64 a23 = *(const u64*)(ap + 2);
        const u64 a45 = *(const u64*)(ap + 4);
        const u64 a67 = *(const u64*)(ap + 6);
        const float* wp = &Ws[k * WP + 2 * l];
        const u64 b0 = *(const u64*)wp;
        const u64 b1 = *(const u64*)(wp + 64);
        const u64 b3 = *(const u64*)(wp + 192);
        float a0, a1, a2f, a3, a4, a5, a6, a7;
        unpack2(a01, a0, a1); unpack2(a23, a2f, a3);
        unpack2(a45, a4, a5); unpack2(a67, a6, a7);
        #define ROWF(i, av) { const u64 aa = pack2(av, av); \
            ac[4*i]   = fma2(aa, b0, ac[4*i]); \
            ac[4*i+1] = fma2(aa, b1, ac[4*i+1]); \
            ac[4*i+3] = fma2(aa, b3, ac[4*i+3]); }
        ROWF(0, a0) ROWF(1, a1) ROWF(2, a2f) ROWF(3, a3)
        ROWF(4, a4) ROWF(5, a5) ROWF(6, a6) ROWF(7, a7)
        #undef ROWF
    }

    // store: thread's gates {2l,2l+1} in each of the 4 blocks, 8 rows (STG.64 coalesced)
    #pragma unroll
    for (int i = 0; i < 8; ++i) {
        float* gp = &g_gates[(rb + 8 * tr + i) * 256 + 2 * l];
        *(u64*)gp         = ac[4*i];
        *(u64*)(gp + 64)  = ac[4*i+1];
        *(u64*)(gp + 128) = ac[4*i+2];
        *(u64*)(gp + 192) = ac[4*i+3];
    }
}

// ================= Kernel E: GRU epilogue + q =================
__global__ void __launch_bounds__(256, 4)
epi_kernel(const float* __restrict__ g_hid,
           const float* __restrict__ b_ih, const float* __restrict__ b_hh,
           const float* __restrict__ w_fc2, const float* __restrict__ b_fc2,
           float* __restrict__ out_q, float* __restrict__ out_h)
{
    __shared__ float sbih[192], sbhh[192], swf[320], sb5[8];
    const int tid = threadIdx.x;
    for (int i = tid; i < 192; i += 256) { sbih[i] = b_ih[i]; sbhh[i] = b_hh[i]; }
    for (int i = tid; i < 320; i += 256) swf[i] = w_fc2[i];
    if (tid < 5) sb5[tid] = b_fc2[tid];
    __syncthreads();

    const int w    = tid >> 5;      // warp -> row within block
    const int lane = tid & 31;
    const size_t row = (size_t)blockIdx.x * 8 + w;
    const float* gp = &g_gates[row * 256];
    const float* hp = g_hid + row * 64;
    float* ho = out_h + row * 64;

    float hq0 = 0.f, hq1 = 0.f, hq2 = 0.f, hq3 = 0.f, hq4 = 0.f;
    #pragma unroll
    for (int jj = 0; jj < 2; ++jj) {
        const int j = lane + 32 * jj;
        const float g0 = gp[j], g1 = gp[64 + j], g2 = gp[128 + j], g3 = gp[192 + j];
        const float r_ = fsig(g0 + sbih[j] + sbhh[j]);
        const float z_ = fsig(g1 + sbih[64 + j] + sbhh[64 + j]);
        const float n_ = ftanh(g2 + sbih[128 + j] + r_ * (g3 + sbhh[128 + j]));
        const float hj = hp[j];
        const float h_ = n_ + z_ * (hj - n_);
        ho[j] = h_;
        hq0 = fmaf(h_, swf[j * 5],     hq0);
        hq1 = fmaf(h_, swf[j * 5 + 1], hq1);
        hq2 = fmaf(h_, swf[j * 5 + 2], hq2);
        hq3 = fmaf(h_, swf[j * 5 + 3], hq3);
        hq4 = fmaf(h_, swf[j * 5 + 4], hq4);
    }
    #pragma unroll
    for (int off = 16; off; off >>= 1) {
        hq0 += __shfl_down_sync(0xffffffffu, hq0, off);
        hq1 += __shfl_down_sync(0xffffffffu, hq1, off);
        hq2 += __shfl_down_sync(0xffffffffu, hq2, off);
        hq3 += __shfl_down_sync(0xffffffffu, hq3, off);
        hq4 += __shfl_down_sync(0xffffffffu, hq4, off);
    }
    if (lane == 0) {
        float* qp = out_q + row * 5;
        qp[0] = hq0 + sb5[0]; qp[1] = hq1 + sb5[1]; qp[2] = hq2 + sb5[2];
        qp[3] = hq3 + sb5[3]; qp[4] = hq4 + sb5[4];
    }
}

extern "C" void kernel_launch(void* const* d_in, const int* in_sizes, int n_in,
                              void* d_out, int out_size)
{
    const float* g_obs  = (const float*)d_in[0];
    const float* g_hid  = (const float*)d_in[1];
    const float* w_in0  = (const float*)d_in[2];
    const float* b_in0  = (const float*)d_in[3];
    const float* w_in1  = (const float*)d_in[4];
    const float* b_in1  = (const float*)d_in[5];
    const float* w_in2  = (const float*)d_in[6];
    const float* b_in2  = (const float*)d_in[7];
    const float* g_W    = (const float*)d_in[8];
    const float* g_a    = (const float*)d_in[9];
    const float* w_o1   = (const float*)d_in[10];
    const float* b_o1   = (const float*)d_in[11];
    const float* w_o2   = (const float*)d_in[12];
    const float* b_o2   = (const float*)d_in[13];
    const float* w_o3   = (const float*)d_in[14];
    const float* b_o3   = (const float*)d_in[15];
    const float* w_fc1  = (const float*)d_in[16];
    const float* b_fc1  = (const float*)d_in[17];
    const float* w_ih   = (const float*)d_in[18];
    const float* w_hh   = (const float*)d_in[19];
    const float* b_ih   = (const float*)d_in[20];
    const float* b_hh   = (const float*)d_in[21];
    const float* w_fc2  = (const float*)d_in[22];
    const float* b_fc2  = (const float*)d_in[23];

    float* out   = (float*)d_out;
    float* out_q = out;                          // q: (65536, 5)
    float* out_h = out + (size_t)65536 * 5;      // h: (65536, 64)

    const int smemA = A_TOT * 4;                 // 91152 B
    const int smemG = G_TOT * 4;                 // 198656 B
    cudaFuncSetAttribute(stageA_kernel, cudaFuncAttributeMaxDynamicSharedMemorySize, smemA);
    cudaFuncSetAttribute(gemm_kernel,   cudaFuncAttributeMaxDynamicSharedMemorySize, smemG);

    stageA_kernel<<<65536 / ROWSA, NBA, smemA>>>(
        g_obs, w_in0, b_in0, w_in1, b_in1, w_in2, b_in2, g_W, g_a,
        w_o1, b_o1, w_o2, b_o2, w_o3, b_o3, w_fc1, b_fc1);

    gemm_kernel<<<65536 / 128, G_THREADS, smemG>>>(g_hid, w_ih, w_hh);

    epi_kernel<<<65536 / 8, 256>>>(g_hid, b_ih, b_hh, w_fc2, b_fc2, out_q, out_h);
}